// round 16
// baseline (speedup 1.0000x reference)
#include <cuda_runtime.h>
#include <cuda_bf16.h>
#include <cstdint>

#define NNODES 50000
#define NEDGES 800000
#define DFEAT  128

// Scratch (no cudaMalloc allowed): agg, h1, h2, rdeg
__device__ float g_agg[NNODES * DFEAT];
__device__ float g_h1 [NNODES * DFEAT];
__device__ float g_h2 [NNODES * DFEAT];
__device__ float g_rdeg[NNODES];

// ---------------------------------------------------------------------------
// zero a float buffer (float4 granularity; counts here are multiples of 4)
__global__ void zero_kernel(float* __restrict__ p, int n4) {
    int i = blockIdx.x * blockDim.x + threadIdx.x;
    if (i < n4) reinterpret_cast<float4*>(p)[i] = make_float4(0.f, 0.f, 0.f, 0.f);
}

// ---------------------------------------------------------------------------
// degree accumulation: deg[row[e]] += ew[e]
__global__ void deg_kernel(const int* __restrict__ ei,
                           const float* __restrict__ ew,
                           float* __restrict__ deg) {
    int e = blockIdx.x * blockDim.x + threadIdx.x;
    if (e < NEDGES) atomicAdd(&deg[ei[e]], ew[e]);
}

// rdeg[i] = 1 / max(deg[i], 1)
__global__ void rdeg_kernel(float* __restrict__ deg) {
    int i = blockIdx.x * blockDim.x + threadIdx.x;
    if (i < NNODES) deg[i] = 1.f / fmaxf(deg[i], 1.f);
}

// ---------------------------------------------------------------------------
// scatter: agg[row[e], :] += ew[e] * src[col[e], :]
// one warp per edge, one float4 per lane (32 lanes * 4 = 128 feats)
// vector reduction (red.global.add.v4.f32, sm_90+) -> 1 red-op per 16B
__global__ void scatter_kernel(const float* __restrict__ src,
                               const int* __restrict__ ei,
                               const float* __restrict__ ew,
                               float* __restrict__ agg) {
    int e = blockIdx.x * (blockDim.x >> 5) + (threadIdx.x >> 5);
    if (e >= NEDGES) return;
    int lane = threadIdx.x & 31;
    int r = __ldg(&ei[e]);
    int c = __ldg(&ei[NEDGES + e]);
    float w = __ldg(&ew[e]);
    float4 v = *reinterpret_cast<const float4*>(src + (size_t)c * DFEAT + lane * 4);
    float* dst = agg + (size_t)r * DFEAT + lane * 4;
    asm volatile("red.global.add.v4.f32 [%0], {%1,%2,%3,%4};"
                 :: "l"(dst), "f"(v.x * w), "f"(v.y * w), "f"(v.z * w), "f"(v.w * w)
                 : "memory");
}

// ---------------------------------------------------------------------------
// Fused SAGE linear:  out[n, :] = act( [X[n,:] | AGG[n,:]*rdeg[n]] @ W^T + b )
// W is [DOUT, 256] row-major (first 128 cols pair X, last 128 pair AGG).
// 256 threads, TM=64 nodes per CTA, K chunked by 32 with shared tiles.
// Inner product uses packed fma.rn.f32x2 (2 outputs per FMA issue).
template<int DOUT, bool RELU>
__global__ void gemm_kernel(const float* __restrict__ X,
                            const float* __restrict__ AGG,
                            const float* __restrict__ RDEG,
                            const float* __restrict__ W,
                            const float* __restrict__ B,
                            float* __restrict__ OUT) {
    constexpr int TM  = 64;
    constexpr int KT  = 32;
    constexpr int JG  = DOUT / 4;      // j-groups of 4 outputs
    constexpr int NG  = 256 / JG;      // node groups
    constexpr int NPT = TM / NG;       // nodes per thread

    __shared__ float Hs[TM][KT + 4];        // row stride 36 floats = 144B (16B mult)
    __shared__ float Wst[KT][DOUT + 4];     // row stride (DOUT+4) floats (16B mult)
    __shared__ float Rs[TM];

    const int tid   = threadIdx.x;
    const int n0cta = blockIdx.x * TM;
    const int j0    = (tid % JG) * 4;
    const int nbase = (tid / JG) * NPT;

    if (tid < TM) {
        int n = n0cta + tid;
        Rs[tid] = (n < NNODES) ? RDEG[n] : 0.f;
    }

    unsigned long long acc[NPT][2];
#pragma unroll
    for (int i = 0; i < NPT; i++) { acc[i][0] = 0ull; acc[i][1] = 0ull; }

    for (int kc = 0; kc < 256; kc += KT) {
        __syncthreads();
        const bool  isAgg = (kc >= 128);
        const float* src  = isAgg ? AGG : X;
        const int    koff = isAgg ? (kc - 128) : kc;

        // load H tile: TM x KT floats = 512 float4, 2 per thread
#pragma unroll
        for (int r = 0; r < (TM * KT / 4) / 256; r++) {
            int idx = tid + r * 256;
            int row = idx >> 3;          // / (KT/4)
            int c4  = idx & 7;
            int n   = n0cta + row;
            float4 v = make_float4(0.f, 0.f, 0.f, 0.f);
            if (n < NNODES)
                v = *reinterpret_cast<const float4*>(src + (size_t)n * DFEAT + koff + c4 * 4);
            if (isAgg) {
                float rd = Rs[row];
                v.x *= rd; v.y *= rd; v.z *= rd; v.w *= rd;
            }
            *reinterpret_cast<float4*>(&Hs[row][c4 * 4]) = v;
        }

        // load W tile transposed: DOUT x KT -> Wst[k][j]
#pragma unroll
        for (int r = 0; r < (DOUT * KT / 4) / 256; r++) {
            int idx = tid + r * 256;
            int j   = idx >> 3;
            int c4  = idx & 7;
            float4 w = *reinterpret_cast<const float4*>(W + (size_t)j * 256 + kc + c4 * 4);
            Wst[c4 * 4 + 0][j] = w.x;
            Wst[c4 * 4 + 1][j] = w.y;
            Wst[c4 * 4 + 2][j] = w.z;
            Wst[c4 * 4 + 3][j] = w.w;
        }
        __syncthreads();

#pragma unroll
        for (int kk = 0; kk < KT; kk++) {
            ulonglong2 wv = *reinterpret_cast<const ulonglong2*>(&Wst[kk][j0]);
#pragma unroll
            for (int i = 0; i < NPT; i++) {
                float h = Hs[nbase + i][kk];
                unsigned long long hh;
                asm("mov.b64 %0, {%1, %1};" : "=l"(hh) : "f"(h));
                asm("fma.rn.f32x2 %0, %1, %2, %0;" : "+l"(acc[i][0]) : "l"(hh), "l"(wv.x));
                asm("fma.rn.f32x2 %0, %1, %2, %0;" : "+l"(acc[i][1]) : "l"(hh), "l"(wv.y));
            }
        }
    }

    const float4 bv = *reinterpret_cast<const float4*>(B + j0);
#pragma unroll
    for (int i = 0; i < NPT; i++) {
        int n = n0cta + nbase + i;
        if (n >= NNODES) continue;
        float4 o;
        o.x = __uint_as_float((unsigned)(acc[i][0] & 0xffffffffu)) + bv.x;
        o.y = __uint_as_float((unsigned)(acc[i][0] >> 32))         + bv.y;
        o.z = __uint_as_float((unsigned)(acc[i][1] & 0xffffffffu)) + bv.z;
        o.w = __uint_as_float((unsigned)(acc[i][1] >> 32))         + bv.w;
        if (RELU) {
            o.x = fmaxf(o.x, 0.f); o.y = fmaxf(o.y, 0.f);
            o.z = fmaxf(o.z, 0.f); o.w = fmaxf(o.w, 0.f);
        }
        *reinterpret_cast<float4*>(OUT + (size_t)n * DOUT + j0) = o;
    }
}

// ---------------------------------------------------------------------------
extern "C" void kernel_launch(void* const* d_in, const int* in_sizes, int n_in,
                              void* d_out, int out_size) {
    const float* x  = (const float*)d_in[0];
    const int*   ei = (const int*)  d_in[1];
    const float* ew = (const float*)d_in[2];
    const float* W0 = (const float*)d_in[3];
    const float* b0 = (const float*)d_in[4];
    const float* W1 = (const float*)d_in[5];
    const float* b1 = (const float*)d_in[6];
    const float* W2 = (const float*)d_in[7];
    const float* b2 = (const float*)d_in[8];
    float* out = (float*)d_out;

    float *agg, *h1, *h2, *rdeg;
    cudaGetSymbolAddress((void**)&agg,  g_agg);
    cudaGetSymbolAddress((void**)&h1,   g_h1);
    cudaGetSymbolAddress((void**)&h2,   g_h2);
    cudaGetSymbolAddress((void**)&rdeg, g_rdeg);

    const int featN4   = NNODES * DFEAT / 4;            // 1.6M float4
    const int zeroGridF = (featN4 + 255) / 256;
    const int zeroGridD = (NNODES / 4 + 255) / 256;
    const int degGrid   = (NEDGES + 255) / 256;
    const int rdegGrid  = (NNODES + 255) / 256;
    const int scatGrid  = (NEDGES + 7) / 8;              // 8 edges/block (warp per edge)
    const int gemmGrid  = (NNODES + 63) / 64;

    // degree (layer-invariant): deg -> rdeg = 1/max(deg,1)
    zero_kernel<<<zeroGridD, 256>>>(rdeg, NNODES / 4);
    deg_kernel <<<degGrid,  256>>>(ei, ew, rdeg);
    rdeg_kernel<<<rdegGrid, 256>>>(rdeg);

    // layer 0
    zero_kernel   <<<zeroGridF, 256>>>(agg, featN4);
    scatter_kernel<<<scatGrid,  256>>>(x, ei, ew, agg);
    gemm_kernel<128, true><<<gemmGrid, 256>>>(x, agg, rdeg, W0, b0, h1);

    // layer 1
    zero_kernel   <<<zeroGridF, 256>>>(agg, featN4);
    scatter_kernel<<<scatGrid,  256>>>(h1, ei, ew, agg);
    gemm_kernel<128, true><<<gemmGrid, 256>>>(h1, agg, rdeg, W1, b1, h2);

    // layer 2 (no relu, DOUT=64, writes d_out directly)
    zero_kernel   <<<zeroGridF, 256>>>(agg, featN4);
    scatter_kernel<<<scatGrid,  256>>>(h2, ei, ew, agg);
    gemm_kernel<64, false><<<gemmGrid, 256>>>(h2, agg, rdeg, W2, b2, out);
}

// round 17
// speedup vs baseline: 1.4894x; 1.4894x over previous
#include <cuda_runtime.h>
#include <cuda_bf16.h>
#include <cstdint>

#define NNODES 50000
#define NEDGES 800000
#define DFEAT  128
#define NBLK   ((NNODES + 255) / 256)   // 196 scan blocks

// Scratch (no cudaMalloc allowed)
__device__ float g_agg[NNODES * DFEAT];
__device__ float g_h1 [NNODES * DFEAT];
__device__ float g_h2 [NNODES * DFEAT];
__device__ int   g_cnt [NNODES];
__device__ int   g_off [NNODES + 1];
__device__ int   g_fill[NNODES];
__device__ int   g_blk [NBLK];
__device__ int   g_ccol[NEDGES];
__device__ float g_cw  [NEDGES];

// ---------------------------------------------------------------------------
__global__ void zero_int_kernel(int* __restrict__ p, int n) {
    int i = blockIdx.x * blockDim.x + threadIdx.x;
    if (i < n) p[i] = 0;
}

// hist: cnt[row[e]]++
__global__ void hist_kernel(const int* __restrict__ ei, int* __restrict__ cnt) {
    int e = blockIdx.x * blockDim.x + threadIdx.x;
    if (e < NEDGES) atomicAdd(&cnt[ei[e]], 1);
}

// block-local exclusive scan of cnt -> off, block totals -> blk
__global__ void scanA_kernel(const int* __restrict__ cnt,
                             int* __restrict__ off, int* __restrict__ blk) {
    __shared__ int s[256];
    int t = threadIdx.x;
    int i = blockIdx.x * 256 + t;
    int v = (i < NNODES) ? cnt[i] : 0;
    s[t] = v;
    __syncthreads();
#pragma unroll
    for (int d = 1; d < 256; d <<= 1) {
        int x = (t >= d) ? s[t - d] : 0;
        __syncthreads();
        s[t] += x;
        __syncthreads();
    }
    if (i < NNODES) off[i] = s[t] - v;          // exclusive within block
    if (t == 255) blk[blockIdx.x] = s[255];     // block total
}

// exclusive scan of block totals (single block)
__global__ void scanB_kernel(int* __restrict__ blk) {
    __shared__ int s[256];
    int t = threadIdx.x;
    int v = (t < NBLK) ? blk[t] : 0;
    s[t] = v;
    __syncthreads();
#pragma unroll
    for (int d = 1; d < 256; d <<= 1) {
        int x = (t >= d) ? s[t - d] : 0;
        __syncthreads();
        s[t] += x;
        __syncthreads();
    }
    if (t < NBLK) blk[t] = s[t] - v;
}

// add block offsets; copy to fill cursor; cap off[NNODES]
__global__ void scanC_kernel(int* __restrict__ off, const int* __restrict__ blk,
                             int* __restrict__ fill) {
    int i = blockIdx.x * blockDim.x + threadIdx.x;
    if (i < NNODES) {
        int o = off[i] + blk[blockIdx.x * 256 / 256 == 0 ? 0 : 0];  // placeholder, fixed below
    }
}

// (correct version — indexed by same blocking as scanA)
__global__ void scanC2_kernel(int* __restrict__ off, const int* __restrict__ blk,
                              int* __restrict__ fill) {
    int t = threadIdx.x;
    int i = blockIdx.x * 256 + t;
    if (i < NNODES) {
        int o = off[i] + blk[blockIdx.x];
        off[i]  = o;
        fill[i] = o;
    }
    if (i == 0) off[NNODES] = NEDGES;
}

// fill CSR arrays (edge order within a node is atomic-nondeterministic; fp sums
// were already order-nondeterministic with the previous scatter)
__global__ void fill_kernel(const int* __restrict__ ei, const float* __restrict__ ew,
                            int* __restrict__ fill,
                            int* __restrict__ ccol, float* __restrict__ cw) {
    int e = blockIdx.x * blockDim.x + threadIdx.x;
    if (e >= NEDGES) return;
    int r = ei[e];
    int p = atomicAdd(&fill[r], 1);
    ccol[p] = ei[NEDGES + e];
    cw[p]   = ew[e];
}

// ---------------------------------------------------------------------------
// gather-aggregate: one warp per node
//   agg[n,:] = (sum_e w_e * src[col_e,:]) / max(sum_e w_e, 1)
__global__ void gather_kernel(const float* __restrict__ src,
                              const int* __restrict__ off,
                              const int* __restrict__ ccol,
                              const float* __restrict__ cw,
                              float* __restrict__ agg) {
    int n = blockIdx.x * (blockDim.x >> 5) + (threadIdx.x >> 5);
    if (n >= NNODES) return;
    int lane = threadIdx.x & 31;
    int s = __ldg(&off[n]);
    int e = __ldg(&off[n + 1]);

    float4 acc = make_float4(0.f, 0.f, 0.f, 0.f);
    float  sw  = 0.f;

    int j = s;
    for (; j + 2 <= e; j += 2) {
        int   c0 = __ldg(&ccol[j]);     float w0 = __ldg(&cw[j]);
        int   c1 = __ldg(&ccol[j + 1]); float w1 = __ldg(&cw[j + 1]);
        float4 v0 = *reinterpret_cast<const float4*>(src + (size_t)c0 * DFEAT + lane * 4);
        float4 v1 = *reinterpret_cast<const float4*>(src + (size_t)c1 * DFEAT + lane * 4);
        acc.x += w0 * v0.x + w1 * v1.x;
        acc.y += w0 * v0.y + w1 * v1.y;
        acc.z += w0 * v0.z + w1 * v1.z;
        acc.w += w0 * v0.w + w1 * v1.w;
        sw    += w0 + w1;
    }
    if (j < e) {
        int   c0 = __ldg(&ccol[j]); float w0 = __ldg(&cw[j]);
        float4 v0 = *reinterpret_cast<const float4*>(src + (size_t)c0 * DFEAT + lane * 4);
        acc.x += w0 * v0.x; acc.y += w0 * v0.y;
        acc.z += w0 * v0.z; acc.w += w0 * v0.w;
        sw    += w0;
    }

    float rd = 1.f / fmaxf(sw, 1.f);
    acc.x *= rd; acc.y *= rd; acc.z *= rd; acc.w *= rd;
    *reinterpret_cast<float4*>(agg + (size_t)n * DFEAT + lane * 4) = acc;
}

// ---------------------------------------------------------------------------
// Fused SAGE linear:  out[n, :] = act( [X[n,:] | AGG[n,:]] @ W^T + b )
// (AGG is pre-normalized by the gather.)  Packed fma.rn.f32x2 inner product.
template<int DOUT, bool RELU>
__global__ void gemm_kernel(const float* __restrict__ X,
                            const float* __restrict__ AGG,
                            const float* __restrict__ W,
                            const float* __restrict__ B,
                            float* __restrict__ OUT) {
    constexpr int TM  = 64;
    constexpr int KT  = 32;
    constexpr int JG  = DOUT / 4;
    constexpr int NG  = 256 / JG;
    constexpr int NPT = TM / NG;

    __shared__ float Hs[TM][KT + 4];
    __shared__ float Wst[KT][DOUT + 4];

    const int tid   = threadIdx.x;
    const int n0cta = blockIdx.x * TM;
    const int j0    = (tid % JG) * 4;
    const int nbase = (tid / JG) * NPT;

    unsigned long long acc[NPT][2];
#pragma unroll
    for (int i = 0; i < NPT; i++) { acc[i][0] = 0ull; acc[i][1] = 0ull; }

    for (int kc = 0; kc < 256; kc += KT) {
        __syncthreads();
        const float* src  = (kc >= 128) ? AGG : X;
        const int    koff = (kc >= 128) ? (kc - 128) : kc;

#pragma unroll
        for (int r = 0; r < (TM * KT / 4) / 256; r++) {
            int idx = tid + r * 256;
            int row = idx >> 3;
            int c4  = idx & 7;
            int n   = n0cta + row;
            float4 v = make_float4(0.f, 0.f, 0.f, 0.f);
            if (n < NNODES)
                v = *reinterpret_cast<const float4*>(src + (size_t)n * DFEAT + koff + c4 * 4);
            *reinterpret_cast<float4*>(&Hs[row][c4 * 4]) = v;
        }

#pragma unroll
        for (int r = 0; r < (DOUT * KT / 4) / 256; r++) {
            int idx = tid + r * 256;
            int j   = idx >> 3;
            int c4  = idx & 7;
            float4 w = *reinterpret_cast<const float4*>(W + (size_t)j * 256 + kc + c4 * 4);
            Wst[c4 * 4 + 0][j] = w.x;
            Wst[c4 * 4 + 1][j] = w.y;
            Wst[c4 * 4 + 2][j] = w.z;
            Wst[c4 * 4 + 3][j] = w.w;
        }
        __syncthreads();

#pragma unroll
        for (int kk = 0; kk < KT; kk++) {
            ulonglong2 wv = *reinterpret_cast<const ulonglong2*>(&Wst[kk][j0]);
#pragma unroll
            for (int i = 0; i < NPT; i++) {
                float h = Hs[nbase + i][kk];
                unsigned long long hh;
                asm("mov.b64 %0, {%1, %1};" : "=l"(hh) : "f"(h));
                asm("fma.rn.f32x2 %0, %1, %2, %0;" : "+l"(acc[i][0]) : "l"(hh), "l"(wv.x));
                asm("fma.rn.f32x2 %0, %1, %2, %0;" : "+l"(acc[i][1]) : "l"(hh), "l"(wv.y));
            }
        }
    }

    const float4 bv = *reinterpret_cast<const float4*>(B + j0);
#pragma unroll
    for (int i = 0; i < NPT; i++) {
        int n = n0cta + nbase + i;
        if (n >= NNODES) continue;
        float4 o;
        o.x = __uint_as_float((unsigned)(acc[i][0] & 0xffffffffu)) + bv.x;
        o.y = __uint_as_float((unsigned)(acc[i][0] >> 32))         + bv.y;
        o.z = __uint_as_float((unsigned)(acc[i][1] & 0xffffffffu)) + bv.z;
        o.w = __uint_as_float((unsigned)(acc[i][1] >> 32))         + bv.w;
        if (RELU) {
            o.x = fmaxf(o.x, 0.f); o.y = fmaxf(o.y, 0.f);
            o.z = fmaxf(o.z, 0.f); o.w = fmaxf(o.w, 0.f);
        }
        *reinterpret_cast<float4*>(OUT + (size_t)n * DOUT + j0) = o;
    }
}

// ---------------------------------------------------------------------------
extern "C" void kernel_launch(void* const* d_in, const int* in_sizes, int n_in,
                              void* d_out, int out_size) {
    const float* x  = (const float*)d_in[0];
    const int*   ei = (const int*)  d_in[1];
    const float* ew = (const float*)d_in[2];
    const float* W0 = (const float*)d_in[3];
    const float* b0 = (const float*)d_in[4];
    const float* W1 = (const float*)d_in[5];
    const float* b1 = (const float*)d_in[6];
    const float* W2 = (const float*)d_in[7];
    const float* b2 = (const float*)d_in[8];
    float* out = (float*)d_out;

    float *agg, *h1, *h2, *cw;
    int *cnt, *off, *fill, *blk, *ccol;
    cudaGetSymbolAddress((void**)&agg,  g_agg);
    cudaGetSymbolAddress((void**)&h1,   g_h1);
    cudaGetSymbolAddress((void**)&h2,   g_h2);
    cudaGetSymbolAddress((void**)&cnt,  g_cnt);
    cudaGetSymbolAddress((void**)&off,  g_off);
    cudaGetSymbolAddress((void**)&fill, g_fill);
    cudaGetSymbolAddress((void**)&blk,  g_blk);
    cudaGetSymbolAddress((void**)&ccol, g_ccol);
    cudaGetSymbolAddress((void**)&cw,   g_cw);

    const int edgeGrid = (NEDGES + 255) / 256;
    const int nodeGrid = NBLK;                     // 196 (256/CTA)
    const int gathGrid = (NNODES + 7) / 8;         // warp per node
    const int gemmGrid = (NNODES + 63) / 64;

    // ---- build CSR (counting sort by dst row) ----
    zero_int_kernel<<<nodeGrid, 256>>>(cnt, NNODES);
    hist_kernel    <<<edgeGrid, 256>>>(ei, cnt);
    scanA_kernel   <<<nodeGrid, 256>>>(cnt, off, blk);
    scanB_kernel   <<<1,        256>>>(blk);
    scanC2_kernel  <<<nodeGrid, 256>>>(off, blk, fill);
    fill_kernel    <<<edgeGrid, 256>>>(ei, ew, fill, ccol, cw);

    // ---- layer 0 ----
    gather_kernel<<<gathGrid, 256>>>(x, off, ccol, cw, agg);
    gemm_kernel<128, true><<<gemmGrid, 256>>>(x, agg, W0, b0, h1);

    // ---- layer 1 ----
    gather_kernel<<<gathGrid, 256>>>(h1, off, ccol, cw, agg);
    gemm_kernel<128, true><<<gemmGrid, 256>>>(h1, agg, W1, b1, h2);

    // ---- layer 2 (no relu, DOUT=64, writes d_out) ----
    gather_kernel<<<gathGrid, 256>>>(h2, off, ccol, cw, agg);
    gemm_kernel<64, false><<<gemmGrid, 256>>>(h2, agg, W2, b2, out);
}